// round 5
// baseline (speedup 1.0000x reference)
#include <cuda_runtime.h>
#include <cuda_bf16.h>
#include <mma.h>
#include <cstdint>
#include <cfloat>

using namespace nvcuda;

#define B_   256
#define P_   128
#define K_   512
#define HID_ 64
#define EMB_ 1536   // K_ + 1024 (frame)

// ---------------- device scratch ----------------
__device__ float g_qfp[8][B_][HID_];                 // qf partials [d-slice][batch][h]
__device__ __nv_bfloat16 g_Bh[K_ * HID_];            // W1k hi, row-major [k][h]
__device__ __nv_bfloat16 g_Bl[K_ * HID_];            // W1k lo

// ---------------- helpers ----------------
__device__ __forceinline__ uint32_t smem_u32(const void* p) {
    uint32_t a;
    asm("{ .reg .u64 t; cvta.to.shared.u64 t, %1; cvt.u32.u64 %0, t; }" : "=r"(a) : "l"(p));
    return a;
}
__device__ __forceinline__ void cp_async16(uint32_t dst, const void* src) {
    asm volatile("cp.async.cg.shared.global [%0], [%1], 16;" :: "r"(dst), "l"(src) : "memory");
}
#define CP_COMMIT() asm volatile("cp.async.commit_group;" ::: "memory")
#define CP_WAIT0()  asm volatile("cp.async.wait_group 0;" ::: "memory")

union PackB4 { __nv_bfloat16 b[4]; uint2 u; };
__device__ __forceinline__ void split4(float4 v, PackB4& hi, PackB4& lo) {
    #pragma unroll
    for (int q = 0; q < 4; q++) {
        float x = (q == 0) ? v.x : (q == 1) ? v.y : (q == 2) ? v.z : v.w;
        __nv_bfloat16 h = __float2bfloat16(x);
        hi.b[q] = h;
        lo.b[q] = __float2bfloat16(x - __bfloat162float(h));
    }
}

// ---------------- kernel 1: qf projection + W1k pre-split ----------------
// blocks 0..255: qf partials; blocks 256..271: split W1k into g_Bh/g_Bl
__global__ __launch_bounds__(256, 4)
void qf_kernel(const float* __restrict__ query,
               const float* __restrict__ frame,
               const float* __restrict__ W1) {
    if (blockIdx.x >= 256) {
        const int base = (blockIdx.x - 256) * 2048 + threadIdx.x * 8;
        #pragma unroll
        for (int v = 0; v < 2; v++) {
            float4 x = *(const float4*)(W1 + base + v * 4);
            PackB4 hi, lo; split4(x, hi, lo);
            *(uint2*)(g_Bh + base + v * 4) = hi.u;
            *(uint2*)(g_Bl + base + v * 4) = lo.u;
        }
        return;
    }
    __shared__ float sX[8][256];
    const int bg = blockIdx.x & 31;
    const int ds = blockIdx.x >> 5;
    const int t  = threadIdx.x;

    const float* src = (ds < 4) ? (query + ds * 256) : (frame + (ds - 4) * 256);
    #pragma unroll
    for (int j = 0; j < 8; j++) {
        int lin = j * 256 + t;
        int bb = lin >> 8, ff = lin & 255;
        sX[bb][ff] = src[(size_t)(bg * 8 + bb) * 1024 + ff];
    }
    __syncthreads();

    const int h  = t & 63;
    const int bs = t >> 6;
    const float* w = W1 + (size_t)(K_ + ds * 256) * HID_ + h;
    float a0 = 0.f, a1 = 0.f;
    #pragma unroll 8
    for (int d = 0; d < 256; d++) {
        float wv = w[(size_t)d * HID_];
        a0 = fmaf(wv, sX[bs][d],     a0);
        a1 = fmaf(wv, sX[bs + 4][d], a1);
    }
    g_qfp[ds][bg * 8 + bs][h]     = a0;
    g_qfp[ds][bg * 8 + bs + 4][h] = a1;
}

// ---------------- kernel 2: main fused attention ----------------
// SMEM (bytes):
//   [0)       raw A: 128 x 64 f32 = 32768
//   [32768)   sAh: 128 x 72 bf16 = 18432     } aliased by sH (128x68 f32) after GEMM
//   [51200)   sAl: 128 x 72 bf16 = 18432     }
//   [69632)   sB: 2 bufs x (hi 64x72 + lo 64x72) bf16 = 2 x 18432
//   [106496)  sQF 64f | [106752) sW2 64f | [107008) sScore 128f
#define OFF_RAW 0u
#define OFF_AH  32768u
#define OFF_AL  51200u
#define OFF_B   69632u
#define BBUF    18432u
#define OFF_QF  106496u
#define OFF_W2  106752u
#define OFF_SC  107008u
#define SMEM_BYTES 107520
#define LDA 72
#define LDB 72
#define LDH 68

__global__ __launch_bounds__(256, 2)
void attn_main(const float* __restrict__ keys,
               const float* __restrict__ frame,
               const int*   __restrict__ mask,
               const float* __restrict__ W2,
               float* __restrict__ out) {
    extern __shared__ char smem[];
    const uint32_t sb = smem_u32(smem);
    float*         sRaw = (float*)(smem + OFF_RAW);
    __nv_bfloat16* sAh  = (__nv_bfloat16*)(smem + OFF_AH);
    __nv_bfloat16* sAl  = (__nv_bfloat16*)(smem + OFF_AL);
    float* sQF    = (float*)(smem + OFF_QF);
    float* sW2    = (float*)(smem + OFF_W2);
    float* sScore = (float*)(smem + OFF_SC);
    float* sH     = (float*)(smem + OFF_AH);   // alias after GEMM

    const int b = blockIdx.x;
    const int t = threadIdx.x;
    const int wid = t >> 5;
    const float* keyb = keys  + (size_t)b * P_ * K_;
    const float* fb   = frame + (size_t)b * 1024;

    // staging geometry
    const int arow = t >> 4;          // A: row base, +16 per i ; float4 col = t&15
    const int ac4  = t & 15;
    const int brow = t >> 3;          // B: row 0..31 (+32 per i) ; 16B col = t&7
    const int bc8  = t & 7;

    // ---- issue chunk 0 (A raw + B buf0) ----
    {
        #pragma unroll
        for (int i = 0; i < 8; i++)
            cp_async16(sb + OFF_RAW + (uint32_t)((arow + 16 * i) * 256 + ac4 * 16),
                       keyb + (size_t)(arow + 16 * i) * K_ + ac4 * 4);
        #pragma unroll
        for (int i = 0; i < 2; i++) {
            int row = brow + 32 * i;
            cp_async16(sb + OFF_B + (uint32_t)(row * (LDB * 2) + bc8 * 16),
                       g_Bh + row * HID_ + bc8 * 8);
            cp_async16(sb + OFF_B + 9216u + (uint32_t)(row * (LDB * 2) + bc8 * 16),
                       g_Bl + row * HID_ + bc8 * 8);
        }
        CP_COMMIT();
    }

    if (t < HID_) {
        float s = 0.f;
        #pragma unroll
        for (int ds = 0; ds < 8; ds++) s += g_qfp[ds][b][t];
        sQF[t] = s;
        sW2[t] = W2[t];
    }

    // ---- GEMM: H[128,64] = keys[b] @ W1k, wmma bf16 3-term split ----
    const int wm = wid & 3;
    const int wn = wid >> 2;
    wmma::fragment<wmma::accumulator, 16, 16, 16, float> acc[2][2];
    #pragma unroll
    for (int i = 0; i < 2; i++)
        #pragma unroll
        for (int j = 0; j < 2; j++) wmma::fill_fragment(acc[i][j], 0.f);

    for (int kc = 0; kc < 8; kc++) {
        const uint32_t bbuf = OFF_B + (kc & 1) * BBUF;
        CP_WAIT0();
        __syncthreads();   // async data visible; prev MMA done (tiles free)

        // convert raw A -> bf16 hi/lo tiles
        #pragma unroll
        for (int i = 0; i < 8; i++) {
            float4 v = *(const float4*)(sRaw + (arow + 16 * i) * 64 + ac4 * 4);
            PackB4 hi, lo; split4(v, hi, lo);
            int eo = (arow + 16 * i) * LDA + ac4 * 4;
            *(uint2*)(sAh + eo) = hi.u;
            *(uint2*)(sAl + eo) = lo.u;
        }
        __syncthreads();   // converts done: raw free, tiles ready

        // issue next chunk (overlaps MMA)
        if (kc < 7) {
            #pragma unroll
            for (int i = 0; i < 8; i++)
                cp_async16(sb + OFF_RAW + (uint32_t)((arow + 16 * i) * 256 + ac4 * 16),
                           keyb + (size_t)(arow + 16 * i) * K_ + (kc + 1) * 64 + ac4 * 4);
            const uint32_t nb = OFF_B + ((kc + 1) & 1) * BBUF;
            #pragma unroll
            for (int i = 0; i < 2; i++) {
                int row = brow + 32 * i;
                cp_async16(sb + nb + (uint32_t)(row * (LDB * 2) + bc8 * 16),
                           g_Bh + (kc + 1) * 64 * HID_ + row * HID_ + bc8 * 8);
                cp_async16(sb + nb + 9216u + (uint32_t)(row * (LDB * 2) + bc8 * 16),
                           g_Bl + (kc + 1) * 64 * HID_ + row * HID_ + bc8 * 8);
            }
            CP_COMMIT();
        }

        const __nv_bfloat16* sBh = (const __nv_bfloat16*)(smem + bbuf);
        const __nv_bfloat16* sBl = (const __nv_bfloat16*)(smem + bbuf + 9216u);
        #pragma unroll
        for (int ks = 0; ks < 4; ks++) {
            wmma::fragment<wmma::matrix_a, 16, 16, 16, __nv_bfloat16, wmma::row_major> ah[2], al[2];
            #pragma unroll
            for (int i = 0; i < 2; i++) {
                wmma::load_matrix_sync(ah[i], sAh + (wm * 32 + i * 16) * LDA + ks * 16, LDA);
                wmma::load_matrix_sync(al[i], sAl + (wm * 32 + i * 16) * LDA + ks * 16, LDA);
            }
            #pragma unroll
            for (int nf = 0; nf < 2; nf++) {
                wmma::fragment<wmma::matrix_b, 16, 16, 16, __nv_bfloat16, wmma::row_major> bh, bl;
                wmma::load_matrix_sync(bh, sBh + (ks * 16) * LDB + wn * 32 + nf * 16, LDB);
                wmma::load_matrix_sync(bl, sBl + (ks * 16) * LDB + wn * 32 + nf * 16, LDB);
                #pragma unroll
                for (int i = 0; i < 2; i++) {
                    wmma::mma_sync(acc[i][nf], ah[i], bh, acc[i][nf]);
                    wmma::mma_sync(acc[i][nf], ah[i], bl, acc[i][nf]);
                    wmma::mma_sync(acc[i][nf], al[i], bh, acc[i][nf]);
                }
            }
        }
    }
    __syncthreads();   // all MMA tile reads done before sH aliases the region

    #pragma unroll
    for (int i = 0; i < 2; i++)
        #pragma unroll
        for (int j = 0; j < 2; j++)
            wmma::store_matrix_sync(sH + (wm * 32 + i * 16) * LDH + wn * 32 + j * 16,
                                    acc[i][j], LDH, wmma::mem_row_major);
    __syncthreads();

    // ---- scores: relu(H + qf) . W2 ----
    if (t < P_) {
        float sc = 0.f;
        const float* hr = sH + t * LDH;
        #pragma unroll
        for (int j = 0; j < HID_; j++) {
            float hv = hr[j] + sQF[j];
            sc = fmaf(fmaxf(hv, 0.f), sW2[j], sc);
        }
        sScore[t] = sc;
    }
    __syncthreads();

    // ---- masked softmax over P (one warp) ----
    if (t < 32) {
        int   mk[4];
        float scv[4], e[4];
        float mx = -FLT_MAX;
        #pragma unroll
        for (int i = 0; i < 4; i++) {
            int p = t + 32 * i;
            mk[i]  = mask[b * P_ + p];
            scv[i] = sScore[p];
            if (mk[i]) mx = fmaxf(mx, scv[i]);
        }
        #pragma unroll
        for (int off = 16; off >= 1; off >>= 1)
            mx = fmaxf(mx, __shfl_xor_sync(0xffffffffu, mx, off));
        float sum = 0.f;
        #pragma unroll
        for (int i = 0; i < 4; i++) { e[i] = mk[i] ? __expf(scv[i] - mx) : 0.f; sum += e[i]; }
        #pragma unroll
        for (int off = 16; off >= 1; off >>= 1)
            sum += __shfl_xor_sync(0xffffffffu, sum, off);
        float inv = 1.0f / sum;
        #pragma unroll
        for (int i = 0; i < 4; i++) {
            int p = t + 32 * i;
            float w = e[i] * inv;
            sScore[p] = w;
            out[(size_t)B_ * EMB_ + (size_t)b * P_ + p] = w;
        }
    }
    __syncthreads();

    // ---- context = weights @ keys (L2-hot) ; embeddings = [context | frame] ----
    {
        float c0 = 0.f, c1 = 0.f, d0 = 0.f, d1 = 0.f;
        #pragma unroll 4
        for (int p = 0; p < P_; p += 2) {
            float wa = sScore[p];
            float wb = sScore[p + 1];
            c0 = fmaf(wa, keyb[(size_t)p * K_ + t],             c0);
            c1 = fmaf(wa, keyb[(size_t)p * K_ + t + 256],       c1);
            d0 = fmaf(wb, keyb[(size_t)(p + 1) * K_ + t],       d0);
            d1 = fmaf(wb, keyb[(size_t)(p + 1) * K_ + t + 256], d1);
        }
        float* eb = out + (size_t)b * EMB_;
        eb[t]       = c0 + d0;
        eb[t + 256] = c1 + d1;
        #pragma unroll
        for (int i = 0; i < 4; i++)
            eb[K_ + t + 256 * i] = fb[t + 256 * i];
    }
}

extern "C" void kernel_launch(void* const* d_in, const int* in_sizes, int n_in,
                              void* d_out, int out_size) {
    const float* query = (const float*)d_in[0];
    const float* keys  = (const float*)d_in[1];
    const float* frame = (const float*)d_in[2];
    const int*   mask  = (const int*)d_in[3];
    const float* W1    = (const float*)d_in[4];
    const float* W2    = (const float*)d_in[5];
    float* out = (float*)d_out;

    static int cfg_done = 0;
    if (!cfg_done) {
        cudaFuncSetAttribute(attn_main, cudaFuncAttributeMaxDynamicSharedMemorySize, SMEM_BYTES);
        cfg_done = 1;
    }

    qf_kernel<<<272, 256>>>(query, frame, W1);
    attn_main<<<B_, 256, SMEM_BYTES>>>(keys, frame, mask, W2, out);
}

// round 6
// speedup vs baseline: 1.4651x; 1.4651x over previous
#include <cuda_runtime.h>
#include <cuda_fp16.h>
#include <mma.h>
#include <cstdint>
#include <cfloat>

using namespace nvcuda;

#define B_   256
#define P_   128
#define K_   512
#define HID_ 64
#define EMB_ 1536   // K_ + 1024 (frame)

// ---------------- device scratch ----------------
__device__ float g_qfp[8][B_][HID_];        // qf partials [d-slice][batch][h]
__device__ __half g_Bh[K_ * HID_];          // W1k hi (fp16), row-major [k][h]
__device__ __half g_Bl[K_ * HID_];          // W1k lo (fp16 residual)

// ---------------- helpers ----------------
__device__ __forceinline__ uint32_t smem_u32(const void* p) {
    uint32_t a;
    asm("{ .reg .u64 t; cvta.to.shared.u64 t, %1; cvt.u32.u64 %0, t; }" : "=r"(a) : "l"(p));
    return a;
}
__device__ __forceinline__ void cp_async16(uint32_t dst, const void* src) {
    asm volatile("cp.async.cg.shared.global [%0], [%1], 16;" :: "r"(dst), "l"(src) : "memory");
}
#define CP_COMMIT()  asm volatile("cp.async.commit_group;" ::: "memory")
#define CP_WAIT(n)   asm volatile("cp.async.wait_group %0;" :: "n"(n) : "memory")

union PackH4 { __half h[4]; uint2 u; };

// ---------------- kernel 1: qf projection + W1k fp16 pre-split ----------------
// blocks 0..255: qf partials; blocks 256..271: split W1k into g_Bh/g_Bl
__global__ __launch_bounds__(256, 4)
void qf_kernel(const float* __restrict__ query,
               const float* __restrict__ frame,
               const float* __restrict__ W1) {
    if (blockIdx.x >= 256) {
        const int base = (blockIdx.x - 256) * 2048 + threadIdx.x * 8;
        PackH4 hi[2], lo[2];
        #pragma unroll
        for (int v = 0; v < 2; v++) {
            float4 x = *(const float4*)(W1 + base + v * 4);
            #pragma unroll
            for (int q = 0; q < 4; q++) {
                float xv = (q == 0) ? x.x : (q == 1) ? x.y : (q == 2) ? x.z : x.w;
                __half h = __float2half_rn(xv);
                hi[v].h[q] = h;
                lo[v].h[q] = __float2half_rn(xv - __half2float(h));
            }
        }
        *(uint4*)(g_Bh + base) = make_uint4(hi[0].u.x, hi[0].u.y, hi[1].u.x, hi[1].u.y);
        *(uint4*)(g_Bl + base) = make_uint4(lo[0].u.x, lo[0].u.y, lo[1].u.x, lo[1].u.y);
        return;
    }
    __shared__ float sX[8][256];
    const int bg = blockIdx.x & 31;
    const int ds = blockIdx.x >> 5;
    const int t  = threadIdx.x;

    const float* src = (ds < 4) ? (query + ds * 256) : (frame + (ds - 4) * 256);
    #pragma unroll
    for (int j = 0; j < 8; j++) {
        int lin = j * 256 + t;
        int bb = lin >> 8, ff = lin & 255;
        sX[bb][ff] = src[(size_t)(bg * 8 + bb) * 1024 + ff];
    }
    __syncthreads();

    const int h  = t & 63;
    const int bs = t >> 6;
    const float* w = W1 + (size_t)(K_ + ds * 256) * HID_ + h;
    float a0 = 0.f, a1 = 0.f;
    #pragma unroll 8
    for (int d = 0; d < 256; d++) {
        float wv = w[(size_t)d * HID_];
        a0 = fmaf(wv, sX[bs][d],     a0);
        a1 = fmaf(wv, sX[bs + 4][d], a1);
    }
    g_qfp[ds][bg * 8 + bs][h]     = a0;
    g_qfp[ds][bg * 8 + bs + 4][h] = a1;
}

// ---------------- kernel 2: main fused attention ----------------
// SMEM (bytes):
//   [0)      sA : 128 x 72 half = 18432     } sH (128x68 f32 = 34816) aliases [0,34816)
//   [18432)  sB : 2 bufs x (hi 64x72 + lo 64x72) half = 2 x 18432 = 36864
//   [55296)  sQF 64f | [55552) sW2 64f | [55808) sScore 128f
#define OFF_A   0u
#define OFF_B   18432u
#define BBUF    18432u
#define BHALF   9216u
#define OFF_QF  55296u
#define OFF_W2  55552u
#define OFF_SC  55808u
#define SMEM_BYTES 56320
#define LDA 72
#define LDB 72
#define LDH 68

__global__ __launch_bounds__(256, 2)
void attn_main(const float* __restrict__ keys,
               const float* __restrict__ frame,
               const int*   __restrict__ mask,
               const float* __restrict__ W2,
               float* __restrict__ out) {
    extern __shared__ char smem[];
    const uint32_t sb = smem_u32(smem);
    __half* sA    = (__half*)(smem + OFF_A);
    float* sQF    = (float*)(smem + OFF_QF);
    float* sW2    = (float*)(smem + OFF_W2);
    float* sScore = (float*)(smem + OFF_SC);
    float* sH     = (float*)(smem + OFF_A);   // alias after GEMM

    const int b = blockIdx.x;
    const int t = threadIdx.x;
    const int wid = t >> 5;
    const float* keyb = keys  + (size_t)b * P_ * K_;
    const float* fb   = frame + (size_t)b * 1024;

    // staging geometry
    const int arow = t >> 4;          // A: row base (+16 per i); float4 col
    const int ac4  = t & 15;
    const int brow = t >> 3;          // B: row 0..31 (+32 per i); 16B col
    const int bc8  = t & 7;

    // ---- prologue: A chunk 0 into registers, B buf0 via cp.async (group 0) ----
    float4 ra[8];
    #pragma unroll
    for (int i = 0; i < 8; i++)
        ra[i] = *(const float4*)(keyb + (size_t)(arow + 16 * i) * K_ + ac4 * 4);
    #pragma unroll
    for (int i = 0; i < 2; i++) {
        int row = brow + 32 * i;
        cp_async16(sb + OFF_B + (uint32_t)(row * (LDB * 2) + bc8 * 16),
                   g_Bh + row * HID_ + bc8 * 8);
        cp_async16(sb + OFF_B + BHALF + (uint32_t)(row * (LDB * 2) + bc8 * 16),
                   g_Bl + row * HID_ + bc8 * 8);
    }
    CP_COMMIT();

    if (t < HID_) {
        float s = 0.f;
        #pragma unroll
        for (int ds = 0; ds < 8; ds++) s += g_qfp[ds][b][t];
        sQF[t] = s;
        sW2[t] = W2[t];
    }

    // ---- GEMM: H[128,64] = keys(fp16) @ (Bh + Bl), 2-term fp16 ----
    const int wm = wid & 3;
    const int wn = wid >> 2;
    wmma::fragment<wmma::accumulator, 16, 16, 16, float> acc[2][2];
    #pragma unroll
    for (int i = 0; i < 2; i++)
        #pragma unroll
        for (int j = 0; j < 2; j++) wmma::fill_fragment(acc[i][j], 0.f);

    for (int kc = 0; kc < 8; kc++) {
        const uint32_t bbuf = OFF_B + (kc & 1) * BBUF;

        // convert prefetched A registers -> fp16 tile
        #pragma unroll
        for (int i = 0; i < 8; i++) {
            PackH4 p;
            p.h[0] = __float2half_rn(ra[i].x);
            p.h[1] = __float2half_rn(ra[i].y);
            p.h[2] = __float2half_rn(ra[i].z);
            p.h[3] = __float2half_rn(ra[i].w);
            *(uint2*)(sA + (arow + 16 * i) * LDA + ac4 * 4) = p.u;
        }

        // issue next chunk (B cp.async + A register prefetch), overlaps MMA
        if (kc < 7) {
            const uint32_t nb = OFF_B + ((kc + 1) & 1) * BBUF;
            #pragma unroll
            for (int i = 0; i < 2; i++) {
                int row = brow + 32 * i;
                cp_async16(sb + nb + (uint32_t)(row * (LDB * 2) + bc8 * 16),
                           g_Bh + (kc + 1) * 64 * HID_ + row * HID_ + bc8 * 8);
                cp_async16(sb + nb + BHALF + (uint32_t)(row * (LDB * 2) + bc8 * 16),
                           g_Bl + (kc + 1) * 64 * HID_ + row * HID_ + bc8 * 8);
            }
            CP_COMMIT();
            #pragma unroll
            for (int i = 0; i < 8; i++)
                ra[i] = *(const float4*)(keyb + (size_t)(arow + 16 * i) * K_ + (kc + 1) * 64 + ac4 * 4);
            CP_WAIT(1);   // buf kc complete (newest group still pending)
        } else {
            CP_WAIT(0);
        }
        __syncthreads();   // A tile + B buf visible to all

        const __half* sBh = (const __half*)(smem + bbuf);
        const __half* sBl = (const __half*)(smem + bbuf + BHALF);
        #pragma unroll
        for (int ks = 0; ks < 4; ks++) {
            wmma::fragment<wmma::matrix_a, 16, 16, 16, __half, wmma::row_major> a[2];
            #pragma unroll
            for (int i = 0; i < 2; i++)
                wmma::load_matrix_sync(a[i], sA + (wm * 32 + i * 16) * LDA + ks * 16, LDA);
            #pragma unroll
            for (int nf = 0; nf < 2; nf++) {
                wmma::fragment<wmma::matrix_b, 16, 16, 16, __half, wmma::row_major> bh, bl;
                wmma::load_matrix_sync(bh, sBh + (ks * 16) * LDB + wn * 32 + nf * 16, LDB);
                wmma::load_matrix_sync(bl, sBl + (ks * 16) * LDB + wn * 32 + nf * 16, LDB);
                #pragma unroll
                for (int i = 0; i < 2; i++) {
                    wmma::mma_sync(acc[i][nf], a[i], bh, acc[i][nf]);
                    wmma::mma_sync(acc[i][nf], a[i], bl, acc[i][nf]);
                }
            }
        }
        __syncthreads();   // tiles consumed (A rewrite + B buf reuse safe)
    }

    #pragma unroll
    for (int i = 0; i < 2; i++)
        #pragma unroll
        for (int j = 0; j < 2; j++)
            wmma::store_matrix_sync(sH + (wm * 32 + i * 16) * LDH + wn * 32 + j * 16,
                                    acc[i][j], LDH, wmma::mem_row_major);
    __syncthreads();

    // ---- scores: relu(H + qf) . W2 ----
    if (t < P_) {
        float sc = 0.f;
        const float* hr = sH + t * LDH;
        #pragma unroll
        for (int j = 0; j < HID_; j++) {
            float hv = hr[j] + sQF[j];
            sc = fmaf(fmaxf(hv, 0.f), sW2[j], sc);
        }
        sScore[t] = sc;
    }
    __syncthreads();

    // ---- masked softmax over P (one warp) ----
    if (t < 32) {
        int   mk[4];
        float scv[4], e[4];
        float mx = -FLT_MAX;
        #pragma unroll
        for (int i = 0; i < 4; i++) {
            int p = t + 32 * i;
            mk[i]  = mask[b * P_ + p];
            scv[i] = sScore[p];
            if (mk[i]) mx = fmaxf(mx, scv[i]);
        }
        #pragma unroll
        for (int off = 16; off >= 1; off >>= 1)
            mx = fmaxf(mx, __shfl_xor_sync(0xffffffffu, mx, off));
        float sum = 0.f;
        #pragma unroll
        for (int i = 0; i < 4; i++) { e[i] = mk[i] ? __expf(scv[i] - mx) : 0.f; sum += e[i]; }
        #pragma unroll
        for (int off = 16; off >= 1; off >>= 1)
            sum += __shfl_xor_sync(0xffffffffu, sum, off);
        float inv = 1.0f / sum;
        #pragma unroll
        for (int i = 0; i < 4; i++) {
            int p = t + 32 * i;
            float w = e[i] * inv;
            sScore[p] = w;
            out[(size_t)B_ * EMB_ + (size_t)b * P_ + p] = w;
        }
    }
    __syncthreads();

    // ---- context = weights @ keys (L2-hot) ; embeddings = [context | frame] ----
    {
        float c0 = 0.f, c1 = 0.f, d0 = 0.f, d1 = 0.f;
        #pragma unroll 4
        for (int p = 0; p < P_; p += 2) {
            float wa = sScore[p];
            float wb = sScore[p + 1];
            c0 = fmaf(wa, keyb[(size_t)p * K_ + t],             c0);
            c1 = fmaf(wa, keyb[(size_t)p * K_ + t + 256],       c1);
            d0 = fmaf(wb, keyb[(size_t)(p + 1) * K_ + t],       d0);
            d1 = fmaf(wb, keyb[(size_t)(p + 1) * K_ + t + 256], d1);
        }
        float* eb = out + (size_t)b * EMB_;
        eb[t]       = c0 + d0;
        eb[t + 256] = c1 + d1;
        #pragma unroll
        for (int i = 0; i < 4; i++)
            eb[K_ + t + 256 * i] = fb[t + 256 * i];
    }
}

extern "C" void kernel_launch(void* const* d_in, const int* in_sizes, int n_in,
                              void* d_out, int out_size) {
    const float* query = (const float*)d_in[0];
    const float* keys  = (const float*)d_in[1];
    const float* frame = (const float*)d_in[2];
    const int*   mask  = (const int*)d_in[3];
    const float* W1    = (const float*)d_in[4];
    const float* W2    = (const float*)d_in[5];
    float* out = (float*)d_out;

    static int cfg_done = 0;
    if (!cfg_done) {
        cudaFuncSetAttribute(attn_main, cudaFuncAttributeMaxDynamicSharedMemorySize, SMEM_BYTES);
        cfg_done = 1;
    }

    qf_kernel<<<272, 256>>>(query, frame, W1);
    attn_main<<<B_, 256, SMEM_BYTES>>>(keys, frame, mask, W2, out);
}

// round 7
// speedup vs baseline: 1.6423x; 1.1209x over previous
#include <cuda_runtime.h>
#include <cuda_fp16.h>
#include <mma.h>
#include <cstdint>
#include <cfloat>

using namespace nvcuda;

#define B_   256
#define P_   128
#define K_   512
#define HID_ 64
#define EMB_ 1536   // K_ + 1024 (frame)

// ---------------- device scratch ----------------
__device__ __half g_Bf[K_ * HID_];   // W1k as fp16, row-major [k][h]

// ---------------- helpers ----------------
__device__ __forceinline__ uint32_t smem_u32(const void* p) {
    uint32_t a;
    asm("{ .reg .u64 t; cvta.to.shared.u64 t, %1; cvt.u32.u64 %0, t; }" : "=r"(a) : "l"(p));
    return a;
}
__device__ __forceinline__ void cp_async16(uint32_t dst, const void* src) {
    asm volatile("cp.async.cg.shared.global [%0], [%1], 16;" :: "r"(dst), "l"(src) : "memory");
}
#define CP_COMMIT()  asm volatile("cp.async.commit_group;" ::: "memory")
#define CP_WAIT(n)   asm volatile("cp.async.wait_group %0;" :: "n"(n) : "memory")

union PackH4 { __half h[4]; uint2 u; };

// ---------------- kernel 1 (tiny): W1k -> fp16 ----------------
__global__ __launch_bounds__(256, 4)
void prep_kernel(const float* __restrict__ W1) {
    const int base = blockIdx.x * 2048 + threadIdx.x * 8;
    PackH4 p[2];
    #pragma unroll
    for (int v = 0; v < 2; v++) {
        float4 x = *(const float4*)(W1 + base + v * 4);
        p[v].h[0] = __float2half_rn(x.x);
        p[v].h[1] = __float2half_rn(x.y);
        p[v].h[2] = __float2half_rn(x.z);
        p[v].h[3] = __float2half_rn(x.w);
    }
    *(uint4*)(g_Bf + base) = make_uint4(p[0].u.x, p[0].u.y, p[1].u.x, p[1].u.y);
}

// ---------------- kernel 2: fully fused attention ----------------
// SMEM (bytes):
//   [0)      sA  : 128 x 72 half = 18432   } sH (128x68 f32 = 34816) aliases [0,34816)
//   [34816)  sB  : 2 bufs x 64 x 72 half = 2 x 9216 = 18432
//   [53248)  sX  : 2048 f32 = 8192            ([query[b] | frame[b]])
//   [61440)  sQFP: 16 x 64 f32 = 4096         (qf partials per d-slice)
//   [65536)  sQF 64f | [65792) sW2 64f | [66048) sScore 128f
#define OFF_A    0u
#define OFF_B    34816u
#define BBUF     9216u
#define OFF_X    53248u
#define OFF_QFP  61440u
#define OFF_QF   65536u
#define OFF_W2   65792u
#define OFF_SC   66048u
#define SMEM_BYTES 66560
#define LDA 72
#define LDB 72
#define LDH 68

__global__ __launch_bounds__(256, 2)
void attn_main(const float* __restrict__ query,
               const float* __restrict__ keys,
               const float* __restrict__ frame,
               const int*   __restrict__ mask,
               const float* __restrict__ W1,
               const float* __restrict__ W2,
               float* __restrict__ out) {
    extern __shared__ char smem[];
    const uint32_t sb = smem_u32(smem);
    __half* sA    = (__half*)(smem + OFF_A);
    float* sX     = (float*)(smem + OFF_X);
    float* sQFP   = (float*)(smem + OFF_QFP);
    float* sQF    = (float*)(smem + OFF_QF);
    float* sW2    = (float*)(smem + OFF_W2);
    float* sScore = (float*)(smem + OFF_SC);
    float* sH     = (float*)(smem + OFF_A);   // alias after GEMM

    const int b = blockIdx.x;
    const int t = threadIdx.x;
    const int wid = t >> 5;
    const float* keyb = keys + (size_t)b * P_ * K_;

    // staging geometry
    const int arow = t >> 4;          // A: row base (+16 per i); float4 col
    const int ac4  = t & 15;
    const int brow = t >> 3;          // B: row 0..31 (+32 per i); 16B col
    const int bc8  = t & 7;
    // qf geometry: thread owns h-quad h4 and d-slice p16
    const int h4   = (t & 15) * 4;
    const int p16  = t >> 4;

    // ---- prologue ----
    // stage x = [query[b] | frame[b]] (2 float4 per thread)
    {
        float4 v0 = *(const float4*)(query + (size_t)b * 1024 + t * 4);
        float4 v1 = *(const float4*)(frame + (size_t)b * 1024 + t * 4);
        *(float4*)(sX + t * 4)        = v0;
        *(float4*)(sX + 1024 + t * 4) = v1;
    }
    // A chunk 0 into registers
    float4 ra[8];
    #pragma unroll
    for (int i = 0; i < 8; i++)
        ra[i] = *(const float4*)(keyb + (size_t)(arow + 16 * i) * K_ + ac4 * 4);
    // B buf0 via cp.async
    #pragma unroll
    for (int i = 0; i < 2; i++) {
        int row = brow + 32 * i;
        cp_async16(sb + OFF_B + (uint32_t)(row * (LDB * 2) + bc8 * 16),
                   g_Bf + row * HID_ + bc8 * 8);
    }
    CP_COMMIT();
    if (t < HID_) sW2[t] = W2[t];

    // ---- GEMM + interleaved qf projection ----
    const int wm = wid & 3;
    const int wn = wid >> 2;
    wmma::fragment<wmma::accumulator, 16, 16, 16, float> acc[2][2];
    #pragma unroll
    for (int i = 0; i < 2; i++)
        #pragma unroll
        for (int j = 0; j < 2; j++) wmma::fill_fragment(acc[i][j], 0.f);

    float qf0 = 0.f, qf1 = 0.f, qf2 = 0.f, qf3 = 0.f;
    __syncthreads();   // sX staged (needed by qf segments)

    for (int kc = 0; kc < 8; kc++) {
        const uint32_t bbuf = OFF_B + (kc & 1) * BBUF;

        // convert prefetched A registers -> fp16 tile
        #pragma unroll
        for (int i = 0; i < 8; i++) {
            PackH4 p;
            p.h[0] = __float2half_rn(ra[i].x);
            p.h[1] = __float2half_rn(ra[i].y);
            p.h[2] = __float2half_rn(ra[i].z);
            p.h[3] = __float2half_rn(ra[i].w);
            *(uint2*)(sA + (arow + 16 * i) * LDA + ac4 * 4) = p.u;
        }

        // issue next chunk (B cp.async + A register prefetch), overlaps MMA
        if (kc < 7) {
            const uint32_t nb = OFF_B + ((kc + 1) & 1) * BBUF;
            #pragma unroll
            for (int i = 0; i < 2; i++) {
                int row = brow + 32 * i;
                cp_async16(sb + nb + (uint32_t)(row * (LDB * 2) + bc8 * 16),
                           g_Bf + (kc + 1) * 64 * HID_ + row * HID_ + bc8 * 8);
            }
            CP_COMMIT();
            #pragma unroll
            for (int i = 0; i < 8; i++)
                ra[i] = *(const float4*)(keyb + (size_t)(arow + 16 * i) * K_ + (kc + 1) * 64 + ac4 * 4);
        }

        // qf segment: 16 of this thread's 128 d's (overlaps tensor work)
        {
            const int dbase = p16 * 128 + kc * 16;
            #pragma unroll
            for (int ii = 0; ii < 16; ii++) {
                int d = dbase + ii;
                float4 w4 = *(const float4*)(W1 + (size_t)(K_ + d) * HID_ + h4);
                float xv = sX[d];
                qf0 = fmaf(xv, w4.x, qf0);
                qf1 = fmaf(xv, w4.y, qf1);
                qf2 = fmaf(xv, w4.z, qf2);
                qf3 = fmaf(xv, w4.w, qf3);
            }
        }

        if (kc < 7) CP_WAIT(1); else CP_WAIT(0);
        __syncthreads();   // A tile + B buf visible

        const __half* sB = (const __half*)(smem + bbuf);
        #pragma unroll
        for (int ks = 0; ks < 4; ks++) {
            wmma::fragment<wmma::matrix_a, 16, 16, 16, __half, wmma::row_major> a[2];
            #pragma unroll
            for (int i = 0; i < 2; i++)
                wmma::load_matrix_sync(a[i], sA + (wm * 32 + i * 16) * LDA + ks * 16, LDA);
            #pragma unroll
            for (int nf = 0; nf < 2; nf++) {
                wmma::fragment<wmma::matrix_b, 16, 16, 16, __half, wmma::row_major> bf;
                wmma::load_matrix_sync(bf, sB + (ks * 16) * LDB + wn * 32 + nf * 16, LDB);
                #pragma unroll
                for (int i = 0; i < 2; i++)
                    wmma::mma_sync(acc[i][nf], a[i], bf, acc[i][nf]);
            }
        }
        __syncthreads();   // tiles consumed
    }

    // qf partials -> smem, reduce 16 slices per h
    sQFP[p16 * 64 + h4 + 0] = qf0;
    sQFP[p16 * 64 + h4 + 1] = qf1;
    sQFP[p16 * 64 + h4 + 2] = qf2;
    sQFP[p16 * 64 + h4 + 3] = qf3;

    #pragma unroll
    for (int i = 0; i < 2; i++)
        #pragma unroll
        for (int j = 0; j < 2; j++)
            wmma::store_matrix_sync(sH + (wm * 32 + i * 16) * LDH + wn * 32 + j * 16,
                                    acc[i][j], LDH, wmma::mem_row_major);
    __syncthreads();

    if (t < HID_) {
        float s = 0.f;
        #pragma unroll
        for (int i = 0; i < 16; i++) s += sQFP[i * 64 + t];
        sQF[t] = s;
    }
    __syncthreads();

    // ---- scores: relu(H + qf) . W2 ----
    if (t < P_) {
        float sc = 0.f;
        const float* hr = sH + t * LDH;
        #pragma unroll
        for (int j = 0; j < HID_; j++) {
            float hv = hr[j] + sQF[j];
            sc = fmaf(fmaxf(hv, 0.f), sW2[j], sc);
        }
        sScore[t] = sc;
    }
    __syncthreads();

    // ---- masked softmax over P (one warp) ----
    if (t < 32) {
        int   mk[4];
        float scv[4], e[4];
        float mx = -FLT_MAX;
        #pragma unroll
        for (int i = 0; i < 4; i++) {
            int p = t + 32 * i;
            mk[i]  = mask[b * P_ + p];
            scv[i] = sScore[p];
            if (mk[i]) mx = fmaxf(mx, scv[i]);
        }
        #pragma unroll
        for (int off = 16; off >= 1; off >>= 1)
            mx = fmaxf(mx, __shfl_xor_sync(0xffffffffu, mx, off));
        float sum = 0.f;
        #pragma unroll
        for (int i = 0; i < 4; i++) { e[i] = mk[i] ? __expf(scv[i] - mx) : 0.f; sum += e[i]; }
        #pragma unroll
        for (int off = 16; off >= 1; off >>= 1)
            sum += __shfl_xor_sync(0xffffffffu, sum, off);
        float inv = 1.0f / sum;
        #pragma unroll
        for (int i = 0; i < 4; i++) {
            int p = t + 32 * i;
            float w = e[i] * inv;
            sScore[p] = w;
            out[(size_t)B_ * EMB_ + (size_t)b * P_ + p] = w;
        }
    }
    __syncthreads();

    // ---- context = weights @ keys (L2-hot) ; embeddings = [context | frame] ----
    {
        float c0 = 0.f, c1 = 0.f, d0 = 0.f, d1 = 0.f;
        #pragma unroll 4
        for (int p = 0; p < P_; p += 2) {
            float wa = sScore[p];
            float wb = sScore[p + 1];
            c0 = fmaf(wa, keyb[(size_t)p * K_ + t],             c0);
            c1 = fmaf(wa, keyb[(size_t)p * K_ + t + 256],       c1);
            d0 = fmaf(wb, keyb[(size_t)(p + 1) * K_ + t],       d0);
            d1 = fmaf(wb, keyb[(size_t)(p + 1) * K_ + t + 256], d1);
        }
        float* eb = out + (size_t)b * EMB_;
        eb[t]       = c0 + d0;
        eb[t + 256] = c1 + d1;
        #pragma unroll
        for (int i = 0; i < 4; i++)
            eb[K_ + t + 256 * i] = sX[1024 + t + 256 * i];
    }
}

extern "C" void kernel_launch(void* const* d_in, const int* in_sizes, int n_in,
                              void* d_out, int out_size) {
    const float* query = (const float*)d_in[0];
    const float* keys  = (const float*)d_in[1];
    const float* frame = (const float*)d_in[2];
    const int*   mask  = (const int*)d_in[3];
    const float* W1    = (const float*)d_in[4];
    const float* W2    = (const float*)d_in[5];
    float* out = (float*)d_out;

    static int cfg_done = 0;
    if (!cfg_done) {
        cudaFuncSetAttribute(attn_main, cudaFuncAttributeMaxDynamicSharedMemorySize, SMEM_BYTES);
        cfg_done = 1;
    }

    prep_kernel<<<16, 256>>>(W1);
    attn_main<<<B_, 256, SMEM_BYTES>>>(query, keys, frame, mask, W1, W2, out);
}

// round 8
// speedup vs baseline: 1.6439x; 1.0010x over previous
#include <cuda_runtime.h>
#include <cuda_fp16.h>
#include <mma.h>
#include <cstdint>
#include <cfloat>

using namespace nvcuda;

#define B_   256
#define P_   128
#define K_   512
#define HID_ 64
#define EMB_ 1536   // K_ + 1024 (frame)

// ---------------- device scratch ----------------
__device__ float g_qfp[8][B_][HID_];   // qf partials [d-slice][batch][h]
__device__ __half g_Bf[K_ * HID_];     // W1k as fp16, row-major [k][h]

// ---------------- helpers ----------------
__device__ __forceinline__ uint32_t smem_u32(const void* p) {
    uint32_t a;
    asm("{ .reg .u64 t; cvta.to.shared.u64 t, %1; cvt.u32.u64 %0, t; }" : "=r"(a) : "l"(p));
    return a;
}
__device__ __forceinline__ void cp_async16(uint32_t dst, const void* src) {
    asm volatile("cp.async.cg.shared.global [%0], [%1], 16;" :: "r"(dst), "l"(src) : "memory");
}
#define CP_COMMIT()  asm volatile("cp.async.commit_group;" ::: "memory")
#define CP_WAIT(n)   asm volatile("cp.async.wait_group %0;" :: "n"(n) : "memory")

union PackH4 { __half h[4]; uint2 u; };

// ---------------- kernel 1: qf partials + W1k fp16 convert ----------------
// blocks 0..255: qf partials; blocks 256..271: W1k -> fp16
__global__ __launch_bounds__(256, 4)
void qf_kernel(const float* __restrict__ query,
               const float* __restrict__ frame,
               const float* __restrict__ W1) {
    if (blockIdx.x >= 256) {
        const int base = (blockIdx.x - 256) * 2048 + threadIdx.x * 8;
        PackH4 p[2];
        #pragma unroll
        for (int v = 0; v < 2; v++) {
            float4 x = *(const float4*)(W1 + base + v * 4);
            p[v].h[0] = __float2half_rn(x.x);
            p[v].h[1] = __float2half_rn(x.y);
            p[v].h[2] = __float2half_rn(x.z);
            p[v].h[3] = __float2half_rn(x.w);
        }
        *(uint4*)(g_Bf + base) = make_uint4(p[0].u.x, p[0].u.y, p[1].u.x, p[1].u.y);
        return;
    }
    __shared__ float sX[8][256];
    const int bg = blockIdx.x & 31;
    const int ds = blockIdx.x >> 5;
    const int t  = threadIdx.x;

    const float* src = (ds < 4) ? (query + ds * 256) : (frame + (ds - 4) * 256);
    #pragma unroll
    for (int j = 0; j < 8; j++) {
        int lin = j * 256 + t;
        int bb = lin >> 8, ff = lin & 255;
        sX[bb][ff] = src[(size_t)(bg * 8 + bb) * 1024 + ff];
    }
    __syncthreads();

    const int h  = t & 63;
    const int bs = t >> 6;
    const float* w = W1 + (size_t)(K_ + ds * 256) * HID_ + h;
    float a0 = 0.f, a1 = 0.f;
    #pragma unroll 8
    for (int d = 0; d < 256; d++) {
        float wv = w[(size_t)d * HID_];
        a0 = fmaf(wv, sX[bs][d],     a0);
        a1 = fmaf(wv, sX[bs + 4][d], a1);
    }
    g_qfp[ds][bg * 8 + bs][h]     = a0;
    g_qfp[ds][bg * 8 + bs + 4][h] = a1;
}

// ---------------- kernel 2: main fused attention ----------------
// SMEM (bytes):
//   [0)      sA : 128 x 72 half = 18432   } sH (128x68 f32 = 34816) aliases [0,34816)
//   [34816)  sB : 2 bufs x 64 x 72 half = 2 x 9216 = 18432
//   [53248)  sQF 64f | [53504) sW2 64f | [53760) sScore 128f
#define OFF_A   0u
#define OFF_B   34816u
#define BBUF    9216u
#define OFF_QF  53248u
#define OFF_W2  53504u
#define OFF_SC  53760u
#define SMEM_BYTES 54272
#define LDA 72
#define LDB 72
#define LDH 68

__global__ __launch_bounds__(256, 2)
void attn_main(const float* __restrict__ keys,
               const float* __restrict__ frame,
               const int*   __restrict__ mask,
               const float* __restrict__ W2,
               float* __restrict__ out) {
    extern __shared__ char smem[];
    const uint32_t sb = smem_u32(smem);
    __half* sA    = (__half*)(smem + OFF_A);
    float* sQF    = (float*)(smem + OFF_QF);
    float* sW2    = (float*)(smem + OFF_W2);
    float* sScore = (float*)(smem + OFF_SC);
    float* sH     = (float*)(smem + OFF_A);   // alias after GEMM

    const int b = blockIdx.x;
    const int t = threadIdx.x;
    const int wid = t >> 5;
    const float* keyb = keys  + (size_t)b * P_ * K_;
    const float* fb   = frame + (size_t)b * 1024;

    // staging geometry
    const int arow = t >> 4;          // A: row base (+16 per i); float4 col
    const int ac4  = t & 15;
    const int brow = t >> 3;          // B: row 0..31 (+32 per i); 16B col
    const int bc8  = t & 7;

    // ---- prologue: A chunk 0 into registers, B buf0 via cp.async ----
    float4 ra[8];
    #pragma unroll
    for (int i = 0; i < 8; i++)
        ra[i] = *(const float4*)(keyb + (size_t)(arow + 16 * i) * K_ + ac4 * 4);
    #pragma unroll
    for (int i = 0; i < 2; i++) {
        int row = brow + 32 * i;
        cp_async16(sb + OFF_B + (uint32_t)(row * (LDB * 2) + bc8 * 16),
                   g_Bf + row * HID_ + bc8 * 8);
    }
    CP_COMMIT();

    if (t < HID_) {
        float s = 0.f;
        #pragma unroll
        for (int ds = 0; ds < 8; ds++) s += g_qfp[ds][b][t];
        sQF[t] = s;
        sW2[t] = W2[t];
    }

    // ---- GEMM: H[128,64] = keys(fp16) @ W1k(fp16) ----
    const int wm = wid & 3;
    const int wn = wid >> 2;
    wmma::fragment<wmma::accumulator, 16, 16, 16, float> acc[2][2];
    #pragma unroll
    for (int i = 0; i < 2; i++)
        #pragma unroll
        for (int j = 0; j < 2; j++) wmma::fill_fragment(acc[i][j], 0.f);

    for (int kc = 0; kc < 8; kc++) {
        const uint32_t bbuf = OFF_B + (kc & 1) * BBUF;

        // convert prefetched A registers -> fp16 tile
        #pragma unroll
        for (int i = 0; i < 8; i++) {
            PackH4 p;
            p.h[0] = __float2half_rn(ra[i].x);
            p.h[1] = __float2half_rn(ra[i].y);
            p.h[2] = __float2half_rn(ra[i].z);
            p.h[3] = __float2half_rn(ra[i].w);
            *(uint2*)(sA + (arow + 16 * i) * LDA + ac4 * 4) = p.u;
        }

        // issue next chunk (B cp.async + A register prefetch), overlaps MMA
        if (kc < 7) {
            const uint32_t nb = OFF_B + ((kc + 1) & 1) * BBUF;
            #pragma unroll
            for (int i = 0; i < 2; i++) {
                int row = brow + 32 * i;
                cp_async16(sb + nb + (uint32_t)(row * (LDB * 2) + bc8 * 16),
                           g_Bf + (kc + 1) * 64 * HID_ + row * HID_ + bc8 * 8);
            }
            CP_COMMIT();
            #pragma unroll
            for (int i = 0; i < 8; i++)
                ra[i] = *(const float4*)(keyb + (size_t)(arow + 16 * i) * K_ + (kc + 1) * 64 + ac4 * 4);
            CP_WAIT(1);
        } else {
            CP_WAIT(0);
        }
        __syncthreads();   // A tile + B buf visible

        const __half* sB = (const __half*)(smem + bbuf);
        #pragma unroll
        for (int ks = 0; ks < 4; ks++) {
            wmma::fragment<wmma::matrix_a, 16, 16, 16, __half, wmma::row_major> a[2];
            #pragma unroll
            for (int i = 0; i < 2; i++)
                wmma::load_matrix_sync(a[i], sA + (wm * 32 + i * 16) * LDA + ks * 16, LDA);
            #pragma unroll
            for (int nf = 0; nf < 2; nf++) {
                wmma::fragment<wmma::matrix_b, 16, 16, 16, __half, wmma::row_major> bf;
                wmma::load_matrix_sync(bf, sB + (ks * 16) * LDB + wn * 32 + nf * 16, LDB);
                #pragma unroll
                for (int i = 0; i < 2; i++)
                    wmma::mma_sync(acc[i][nf], a[i], bf, acc[i][nf]);
            }
        }
        __syncthreads();   // tiles consumed
    }

    #pragma unroll
    for (int i = 0; i < 2; i++)
        #pragma unroll
        for (int j = 0; j < 2; j++)
            wmma::store_matrix_sync(sH + (wm * 32 + i * 16) * LDH + wn * 32 + j * 16,
                                    acc[i][j], LDH, wmma::mem_row_major);
    __syncthreads();

    // ---- scores: relu(H + qf) . W2 ----
    if (t < P_) {
        float sc = 0.f;
        const float* hr = sH + t * LDH;
        #pragma unroll
        for (int j = 0; j < HID_; j++) {
            float hv = hr[j] + sQF[j];
            sc = fmaf(fmaxf(hv, 0.f), sW2[j], sc);
        }
        sScore[t] = sc;
    }
    __syncthreads();

    // ---- masked softmax over P (one warp) ----
    if (t < 32) {
        int   mk[4];
        float scv[4], e[4];
        float mx = -FLT_MAX;
        #pragma unroll
        for (int i = 0; i < 4; i++) {
            int p = t + 32 * i;
            mk[i]  = mask[b * P_ + p];
            scv[i] = sScore[p];
            if (mk[i]) mx = fmaxf(mx, scv[i]);
        }
        #pragma unroll
        for (int off = 16; off >= 1; off >>= 1)
            mx = fmaxf(mx, __shfl_xor_sync(0xffffffffu, mx, off));
        float sum = 0.f;
        #pragma unroll
        for (int i = 0; i < 4; i++) { e[i] = mk[i] ? __expf(scv[i] - mx) : 0.f; sum += e[i]; }
        #pragma unroll
        for (int off = 16; off >= 1; off >>= 1)
            sum += __shfl_xor_sync(0xffffffffu, sum, off);
        float inv = 1.0f / sum;
        #pragma unroll
        for (int i = 0; i < 4; i++) {
            int p = t + 32 * i;
            float w = e[i] * inv;
            sScore[p] = w;
            out[(size_t)B_ * EMB_ + (size_t)b * P_ + p] = w;
        }
    }
    __syncthreads();

    // ---- context = weights @ keys (L2-hot) ; embeddings = [context | frame] ----
    {
        float c0 = 0.f, c1 = 0.f, d0 = 0.f, d1 = 0.f;
        #pragma unroll 4
        for (int p = 0; p < P_; p += 2) {
            float wa = sScore[p];
            float wb = sScore[p + 1];
            c0 = fmaf(wa, keyb[(size_t)p * K_ + t],             c0);
            c1 = fmaf(wa, keyb[(size_t)p * K_ + t + 256],       c1);
            d0 = fmaf(wb, keyb[(size_t)(p + 1) * K_ + t],       d0);
            d1 = fmaf(wb, keyb[(size_t)(p + 1) * K_ + t + 256], d1);
        }
        float* eb = out + (size_t)b * EMB_;
        eb[t]       = c0 + d0;
        eb[t + 256] = c1 + d1;
        #pragma unroll
        for (int i = 0; i < 4; i++)
            eb[K_ + t + 256 * i] = fb[t + 256 * i];
    }
}

extern "C" void kernel_launch(void* const* d_in, const int* in_sizes, int n_in,
                              void* d_out, int out_size) {
    const float* query = (const float*)d_in[0];
    const float* keys  = (const float*)d_in[1];
    const float* frame = (const float*)d_in[2];
    const int*   mask  = (const int*)d_in[3];
    const float* W1    = (const float*)d_in[4];
    const float* W2    = (const float*)d_in[5];
    float* out = (float*)d_out;

    static int cfg_done = 0;
    if (!cfg_done) {
        cudaFuncSetAttribute(attn_main, cudaFuncAttributeMaxDynamicSharedMemorySize, SMEM_BYTES);
        cfg_done = 1;
    }

    qf_kernel<<<272, 256>>>(query, frame, W1);
    attn_main<<<B_, 256, SMEM_BYTES>>>(keys, frame, mask, W2, out);
}

// round 10
// speedup vs baseline: 1.9057x; 1.1592x over previous
#include <cuda_runtime.h>
#include <cuda_fp16.h>
#include <mma.h>
#include <cstdint>
#include <cfloat>

using namespace nvcuda;

#define B_   256
#define P_   128
#define K_   512
#define HID_ 64
#define EMB_ 1536   // K_ + 1024 (frame)

// ---------------- device scratch ----------------
__device__ float g_qfp[16][B_][HID_];   // qf partials [d-slice][batch][h]
__device__ __half g_Bf[K_ * HID_];      // W1k as fp16, row-major [k][h]

// ---------------- helpers ----------------
__device__ __forceinline__ uint32_t smem_u32(const void* p) {
    uint32_t a;
    asm("{ .reg .u64 t; cvta.to.shared.u64 t, %1; cvt.u32.u64 %0, t; }" : "=r"(a) : "l"(p));
    return a;
}
__device__ __forceinline__ void cp_async16(uint32_t dst, const void* src) {
    asm volatile("cp.async.cg.shared.global [%0], [%1], 16;" :: "r"(dst), "l"(src) : "memory");
}
#define CP_COMMIT()  asm volatile("cp.async.commit_group;" ::: "memory")
#define CP_WAIT(n)   asm volatile("cp.async.wait_group %0;" :: "n"(n) : "memory")

union PackH4 { __half h[4]; uint2 u; };

// ---------------- kernel 1: qf partials (512 blocks) + W1k fp16 (16 blocks) ----------------
__global__ __launch_bounds__(256, 4)
void qf_kernel(const float* __restrict__ query,
               const float* __restrict__ frame,
               const float* __restrict__ W1) {
    if (blockIdx.x >= 512) {
        const int base = (blockIdx.x - 512) * 2048 + threadIdx.x * 8;
        PackH4 p[2];
        #pragma unroll
        for (int v = 0; v < 2; v++) {
            float4 x = *(const float4*)(W1 + base + v * 4);
            p[v].h[0] = __float2half_rn(x.x);
            p[v].h[1] = __float2half_rn(x.y);
            p[v].h[2] = __float2half_rn(x.z);
            p[v].h[3] = __float2half_rn(x.w);
        }
        *(uint4*)(g_Bf + base) = make_uint4(p[0].u.x, p[0].u.y, p[1].u.x, p[1].u.y);
        return;
    }
    __shared__ float sX[8][128];
    const int bg = blockIdx.x & 31;      // batch group (8 batches)
    const int ds = blockIdx.x >> 5;      // d-slice 0..15 (128 dims each)
    const int t  = threadIdx.x;

    const float* src = (ds < 8) ? (query + ds * 128) : (frame + (ds - 8) * 128);
    #pragma unroll
    for (int j = 0; j < 4; j++) {
        int lin = j * 256 + t;
        int bb = lin >> 7, ff = lin & 127;
        sX[bb][ff] = src[(size_t)(bg * 8 + bb) * 1024 + ff];
    }
    __syncthreads();

    const int h  = t & 63;
    const int bs = t >> 6;
    const float* w = W1 + (size_t)(K_ + ds * 128) * HID_ + h;
    float a0 = 0.f, a1 = 0.f;
    #pragma unroll 8
    for (int d = 0; d < 128; d++) {
        float wv = w[(size_t)d * HID_];
        a0 = fmaf(wv, sX[bs][d],     a0);
        a1 = fmaf(wv, sX[bs + 4][d], a1);
    }
    g_qfp[ds][bg * 8 + bs][h]     = a0;
    g_qfp[ds][bg * 8 + bs + 4][h] = a1;
}

// ---------------- kernel 2: main fused attention ----------------
// SMEM (bytes):
//   [0)      sA : 2 bufs x 128 x 72 half = 36864  } sH (128x68 f32 = 34816) aliases [0,34816)
//   [36864)  sB : 3 bufs x 64 x 72 half = 27648   (triple buffer: cp target never aliases live read)
//   [64512)  sQF 64f | [64768) sW2 64f | [65024) sScore 128f
//   [65536)  sCtx : 1024 f32 = 4096
#define OFF_A   0u
#define ABUF    18432u
#define OFF_B   36864u
#define BBUF    9216u
#define OFF_QF  64512u
#define OFF_W2  64768u
#define OFF_SC  65024u
#define OFF_CTX 65536u
#define SMEM_BYTES 69632
#define LDA 72
#define LDB 72
#define LDH 68

__global__ __launch_bounds__(256, 2)
void attn_main(const float* __restrict__ keys,
               const float* __restrict__ frame,
               const int*   __restrict__ mask,
               const float* __restrict__ W2,
               float* __restrict__ out) {
    extern __shared__ char smem[];
    const uint32_t sb = smem_u32(smem);
    float* sQF    = (float*)(smem + OFF_QF);
    float* sW2    = (float*)(smem + OFF_W2);
    float* sScore = (float*)(smem + OFF_SC);
    float* sCtx   = (float*)(smem + OFF_CTX);
    float* sH     = (float*)(smem + OFF_A);   // alias after GEMM

    const int b = blockIdx.x;
    const int t = threadIdx.x;
    const int wid = t >> 5;
    const float* keyb = keys  + (size_t)b * P_ * K_;
    const float* fb   = frame + (size_t)b * 1024;

    // staging geometry
    const int arow = t >> 4;          // A: row base (+16 per i); float4 col
    const int ac4  = t & 15;
    const int brow = t >> 3;          // B: row 0..31 (+32 per i); 16B col
    const int bc8  = t & 7;

    // ---- prologue ----
    float4 ra[8];
    #pragma unroll
    for (int i = 0; i < 8; i++)                       // LDG chunk 0
        ra[i] = *(const float4*)(keyb + (size_t)(arow + 16 * i) * K_ + ac4 * 4);
    #pragma unroll
    for (int i = 0; i < 2; i++) {                     // cp B0 -> buf 0
        int row = brow + 32 * i;
        cp_async16(sb + OFF_B + (uint32_t)(row * (LDB * 2) + bc8 * 16),
                   g_Bf + row * HID_ + bc8 * 8);
    }
    CP_COMMIT();
    #pragma unroll
    for (int i = 0; i < 2; i++) {                     // cp B1 -> buf 1
        int row = brow + 32 * i;
        cp_async16(sb + OFF_B + BBUF + (uint32_t)(row * (LDB * 2) + bc8 * 16),
                   g_Bf + 64 * HID_ + row * HID_ + bc8 * 8);
    }
    CP_COMMIT();

    if (t < HID_) {
        float s = 0.f;
        #pragma unroll
        for (int ds = 0; ds < 16; ds++) s += g_qfp[ds][b][t];
        sQF[t] = s;
        sW2[t] = W2[t];
    }

    // convert chunk 0 -> sA buf0
    {
        __half* sA0 = (__half*)(smem + OFF_A);
        #pragma unroll
        for (int i = 0; i < 8; i++) {
            PackH4 p;
            p.h[0] = __float2half_rn(ra[i].x);
            p.h[1] = __float2half_rn(ra[i].y);
            p.h[2] = __float2half_rn(ra[i].z);
            p.h[3] = __float2half_rn(ra[i].w);
            *(uint2*)(sA0 + (arow + 16 * i) * LDA + ac4 * 4) = p.u;
        }
    }
    // LDG chunk 1
    #pragma unroll
    for (int i = 0; i < 8; i++)
        ra[i] = *(const float4*)(keyb + (size_t)(arow + 16 * i) * K_ + 64 + ac4 * 4);

    CP_WAIT(1);          // B0 complete (B1 pending)
    __syncthreads();     // sA buf0 + sB buf0 visible; sQF/sW2 staged

    // ---- GEMM mainloop: one barrier per chunk, B triple-buffered ----
    const int wm = wid & 3;
    const int wn = wid >> 2;
    wmma::fragment<wmma::accumulator, 16, 16, 16, float> acc[2][2];
    #pragma unroll
    for (int i = 0; i < 2; i++)
        #pragma unroll
        for (int j = 0; j < 2; j++) wmma::fill_fragment(acc[i][j], 0.f);

    #pragma unroll
    for (int kc = 0; kc < 8; kc++) {
        // convert ra (chunk kc+1) into sA[next]
        if (kc < 7) {
            __half* sAn = (__half*)(smem + OFF_A + ((kc + 1) & 1) * ABUF);
            #pragma unroll
            for (int i = 0; i < 8; i++) {
                PackH4 p;
                p.h[0] = __float2half_rn(ra[i].x);
                p.h[1] = __float2half_rn(ra[i].y);
                p.h[2] = __float2half_rn(ra[i].z);
                p.h[3] = __float2half_rn(ra[i].w);
                *(uint2*)(sAn + (arow + 16 * i) * LDA + ac4 * 4) = p.u;
            }
        }
        // LDG chunk kc+2
        if (kc < 6) {
            #pragma unroll
            for (int i = 0; i < 8; i++)
                ra[i] = *(const float4*)(keyb + (size_t)(arow + 16 * i) * K_ + (kc + 2) * 64 + ac4 * 4);
        }
        // cp B(kc+2) -> buf (kc+2)%3  (disjoint from read buf kc%3 and next (kc+1)%3)
        if (kc < 6) {
            const uint32_t nb = OFF_B + (uint32_t)(((kc + 2) % 3)) * BBUF;
            #pragma unroll
            for (int i = 0; i < 2; i++) {
                int row = brow + 32 * i;
                cp_async16(sb + nb + (uint32_t)(row * (LDB * 2) + bc8 * 16),
                           g_Bf + (kc + 2) * 64 * HID_ + row * HID_ + bc8 * 8);
            }
            CP_COMMIT();
        }

        // MMA on buf kc
        const __half* sA = (const __half*)(smem + OFF_A + (kc & 1) * ABUF);
        const __half* sB = (const __half*)(smem + OFF_B + (kc % 3) * BBUF);
        #pragma unroll
        for (int ks = 0; ks < 4; ks++) {
            wmma::fragment<wmma::matrix_a, 16, 16, 16, __half, wmma::row_major> a[2];
            #pragma unroll
            for (int i = 0; i < 2; i++)
                wmma::load_matrix_sync(a[i], sA + (wm * 32 + i * 16) * LDA + ks * 16, LDA);
            #pragma unroll
            for (int nf = 0; nf < 2; nf++) {
                wmma::fragment<wmma::matrix_b, 16, 16, 16, __half, wmma::row_major> bf;
                wmma::load_matrix_sync(bf, sB + (ks * 16) * LDB + wn * 32 + nf * 16, LDB);
                #pragma unroll
                for (int i = 0; i < 2; i++)
                    wmma::mma_sync(acc[i][nf], a[i], bf, acc[i][nf]);
            }
        }

        if (kc < 6) CP_WAIT(1);      // B(kc+1) done (B(kc+2) pending)
        __syncthreads();             // next bufs visible; this buf free
    }

    #pragma unroll
    for (int i = 0; i < 2; i++)
        #pragma unroll
        for (int j = 0; j < 2; j++)
            wmma::store_matrix_sync(sH + (wm * 32 + i * 16) * LDH + wn * 32 + j * 16,
                                    acc[i][j], LDH, wmma::mem_row_major);
    __syncthreads();

    // ---- scores: relu(H + qf) . W2 ----
    if (t < P_) {
        float sc = 0.f;
        const float* hr = sH + t * LDH;
        #pragma unroll
        for (int j = 0; j < HID_; j++) {
            float hv = hr[j] + sQF[j];
            sc = fmaf(fmaxf(hv, 0.f), sW2[j], sc);
        }
        sScore[t] = sc;
    }
    __syncthreads();

    // ---- masked softmax over P (one warp) ----
    if (t < 32) {
        int   mk[4];
        float scv[4], e[4];
        float mx = -FLT_MAX;
        #pragma unroll
        for (int i = 0; i < 4; i++) {
            int p = t + 32 * i;
            mk[i]  = mask[b * P_ + p];
            scv[i] = sScore[p];
            if (mk[i]) mx = fmaxf(mx, scv[i]);
        }
        #pragma unroll
        for (int off = 16; off >= 1; off >>= 1)
            mx = fmaxf(mx, __shfl_xor_sync(0xffffffffu, mx, off));
        float sum = 0.f;
        #pragma unroll
        for (int i = 0; i < 4; i++) { e[i] = mk[i] ? __expf(scv[i] - mx) : 0.f; sum += e[i]; }
        #pragma unroll
        for (int off = 16; off >= 1; off >>= 1)
            sum += __shfl_xor_sync(0xffffffffu, sum, off);
        float inv = 1.0f / sum;
        #pragma unroll
        for (int i = 0; i < 4; i++) {
            int p = t + 32 * i;
            float w = e[i] * inv;
            sScore[p] = w;
            out[(size_t)B_ * EMB_ + (size_t)b * P_ + p] = w;
        }
    }
    __syncthreads();

    // ---- context = weights @ keys, vectorized split-p ----
    {
        const int th = t & 127;          // float4 col group
        const int ph = (t >> 7) * 64;    // p range start (0 or 64)
        const float* kp = keyb + (size_t)ph * K_ + th * 4;
        float4 cacc = make_float4(0.f, 0.f, 0.f, 0.f);
        #pragma unroll 8
        for (int p = 0; p < 64; p++) {
            float w = sScore[ph + p];
            float4 kv = *(const float4*)(kp + (size_t)p * K_);
            cacc.x = fmaf(w, kv.x, cacc.x);
            cacc.y = fmaf(w, kv.y, cacc.y);
            cacc.z = fmaf(w, kv.z, cacc.z);
            cacc.w = fmaf(w, kv.w, cacc.w);
        }
        *(float4*)(sCtx + (t >> 7) * 512 + th * 4) = cacc;
    }
    __syncthreads();
    {
        float* eb = out + (size_t)b * EMB_;
        if (t < 128) {
            float4 a = *(const float4*)(sCtx + t * 4);
            float4 c = *(const float4*)(sCtx + 512 + t * 4);
            a.x += c.x; a.y += c.y; a.z += c.z; a.w += c.w;
            *(float4*)(eb + t * 4) = a;
        }
        #pragma unroll
        for (int i = 0; i < 4; i++)
            eb[K_ + t + 256 * i] = fb[t + 256 * i];
    }
}

extern "C" void kernel_launch(void* const* d_in, const int* in_sizes, int n_in,
                              void* d_out, int out_size) {
    const float* query = (const float*)d_in[0];
    const float* keys  = (const float*)d_in[1];
    const float* frame = (const float*)d_in[2];
    const int*   mask  = (const int*)d_in[3];
    const float* W1    = (const float*)d_in[4];
    const float* W2    = (const float*)d_in[5];
    float* out = (float*)d_out;

    static int cfg_done = 0;
    if (!cfg_done) {
        cudaFuncSetAttribute(attn_main, cudaFuncAttributeMaxDynamicSharedMemorySize, SMEM_BYTES);
        cfg_done = 1;
    }

    qf_kernel<<<528, 256>>>(query, frame, W1);
    attn_main<<<B_, 256, SMEM_BYTES>>>(keys, frame, mask, W2, out);
}